// round 1
// baseline (speedup 1.0000x reference)
#include <cuda_runtime.h>
#include <cuda_bf16.h>
#include <math.h>

// Problem constants
#define BATCH 2
#define CH 4
#define HH 64
#define WW 64
#define LL (HH*WW)          // 4096
#define NHEADS 4

// Reverb tiling
#define RB_ROWS 4           // core rows per block
#define RB_BLOCKS (BATCH*16)// 2 batches * 16 tiles

// Attention tiling
#define QCHUNKS 18
#define QPB 228             // 18*228 = 4104 >= 4096

// ---------------- scratch (device globals; no allocation allowed) ----------
__device__ float g_fb[2][BATCH][CH][HH][WW];   // ping-pong feedback buffer
__device__ float g_wet[BATCH][CH][LL];
__device__ float g_q[BATCH][NHEADS][LL];
__device__ float g_k[BATCH][NHEADS][LL];
__device__ float g_v[BATCH][NHEADS][LL];
__device__ float g_attn[BATCH][NHEADS][LL];

struct KTab { float k[4][7]; };

__device__ __forceinline__ float sigm(float x) { return 1.0f / (1.0f + expf(-x)); }

// ---------------------------------------------------------------------------
// Reverb iteration kernel.
// grid = 32 blocks (b = blk>>4, tile = blk&15 -> rows [tile*4, tile*4+4)),
// 256 threads, 1 output pixel per thread (all 4 channels).
// ---------------------------------------------------------------------------
__global__ void reverb_iter_kernel(
    const float* __restrict__ x,
    const float* __restrict__ refl_w,
    const float* __restrict__ refl_d,
    const float* __restrict__ fb_w, const float* __restrict__ fb_b,
    const float* __restrict__ d1_w, const float* __restrict__ d1_b,
    const float* __restrict__ d2_w, const float* __restrict__ d2_b,
    const float* __restrict__ ipw, const float* __restrict__ ipb,
    KTab kt, int iter, float pw8)
{
    __shared__ float sfb[CH][RB_ROWS + 8][WW];   // fb rows r0-4 .. r0+RB_ROWS+3
    __shared__ float sy [CH][RB_ROWS + 2][WW+2]; // delay output rows r0-1..r0+RB_ROWS, padded cols
    __shared__ float swt[CH*CH*9];
    __shared__ float skern[7];

    const int b    = blockIdx.x >> 4;
    const int tile = blockIdx.x & 15;
    const int r0   = tile * RB_ROWS;
    const int tid  = threadIdx.x;

    if (tid < CH*CH*9) swt[tid] = fb_w[tid];
    if (tid < 7) {
        int kidx = (int)floorf(refl_d[iter] * 0.5f);
        kidx = min(max(kidx, 0), 3);
        skern[tid] = kt.k[kidx][tid];
    }

    // ---- load fb tile with +-4 row halo (zero-padded) ----
    const int src_pp = (iter + 1) & 1;
    for (int idx = tid; idx < CH*(RB_ROWS+8)*WW; idx += 256) {
        int w  = idx & 63;
        int t  = idx >> 6;
        int lr = t % (RB_ROWS + 8);
        int c  = t / (RB_ROWS + 8);
        int g  = r0 - 4 + lr;
        float v = 0.0f;
        if (g >= 0 && g < HH) {
            if (iter == 0) v = x[((b*CH + c)*HH + g)*WW + w] * 0.1f;
            else           v = g_fb[src_pp][b][c][g][w];
        }
        sfb[c][lr][w] = v;
    }
    __syncthreads();

    // ---- vertical 7-tap delay: y rows gy = r0-1 .. r0+RB_ROWS ----
    for (int idx = tid; idx < CH*(RB_ROWS+2)*(WW+2); idx += 256) {
        int wp = idx % (WW+2);
        int t  = idx / (WW+2);
        int lr = t % (RB_ROWS + 2);
        int c  = t / (RB_ROWS + 2);
        int gy = r0 - 1 + lr;
        int w  = wp - 1;
        float v = 0.0f;
        if (gy >= 0 && gy < HH && w >= 0 && w < WW) {
            float acc = 0.0f;
            #pragma unroll
            for (int t7 = 0; t7 < 7; t7++)
                acc = fmaf(skern[t7], sfb[c][lr + t7][w], acc);  // fb row gy-3+t7 -> sfb row lr+t7
            v = acc;
        }
        sy[c][lr][wp] = v;
    }
    __syncthreads();

    // ---- 3x3 conv (4->4) + damp MLP + accumulate; 1 pixel per thread ----
    const int lr = tid >> 6;         // 0..RB_ROWS-1
    const int w  = tid & 63;
    const int gy = r0 + lr;

    float refl[CH];
    #pragma unroll
    for (int co = 0; co < CH; co++) refl[co] = __ldg(&fb_b[co]);

    #pragma unroll
    for (int ci = 0; ci < CH; ci++) {
        float p[9];
        #pragma unroll
        for (int dy = 0; dy < 3; dy++)
            #pragma unroll
            for (int dx = 0; dx < 3; dx++)
                p[dy*3+dx] = sy[ci][lr + dy][w + dx];
        #pragma unroll
        for (int co = 0; co < CH; co++)
            #pragma unroll
            for (int kk = 0; kk < 9; kk++)
                refl[co] = fmaf(swt[(co*CH + ci)*9 + kk], p[kk], refl[co]);
    }

    // damp = sigmoid(d2(silu(d1(refl))))
    float s1[2];
    #pragma unroll
    for (int j = 0; j < 2; j++) {
        float h1 = __ldg(&d1_b[j]);
        #pragma unroll
        for (int c = 0; c < CH; c++) h1 = fmaf(__ldg(&d1_w[j*CH + c]), refl[c], h1);
        s1[j] = h1 * sigm(h1);
    }
    #pragma unroll
    for (int c = 0; c < CH; c++) {
        float h2 = __ldg(&d2_b[c]);
        #pragma unroll
        for (int j = 0; j < 2; j++) h2 = fmaf(__ldg(&d2_w[c*2 + j]), s1[j], h2);
        refl[c] *= sigm(h2);
    }

    const float wgt = pw8 * sigm(__ldg(&refl_w[iter]));
    const int pix = gy * WW + w;
    const int dst_pp = iter & 1;

    float wv[CH];
    #pragma unroll
    for (int c = 0; c < CH; c++) {
        float prev = (iter == 0) ? 0.0f : g_wet[b][c][pix];
        wv[c] = fmaf(refl[c], wgt, prev);
        g_wet[b][c][pix] = wv[c];
        g_fb[dst_pp][b][c][gy][w] = fmaf(refl[c], 0.04f, sfb[c][lr + 4][w]);
    }

    // last iteration: fuse the qkv projection (head_dim = 1 -> channel h of each group)
    if (iter == 7) {
        #pragma unroll
        for (int h = 0; h < NHEADS; h++) {
            float qv = __ldg(&ipb[h]);
            float kv = __ldg(&ipb[4 + h]);
            float vv = __ldg(&ipb[8 + h]);
            #pragma unroll
            for (int c = 0; c < CH; c++) {
                qv = fmaf(__ldg(&ipw[h*CH + c]),       wv[c], qv);
                kv = fmaf(__ldg(&ipw[(4 + h)*CH + c]), wv[c], kv);
                vv = fmaf(__ldg(&ipw[(8 + h)*CH + c]), wv[c], vv);
            }
            g_q[b][h][pix] = qv;
            g_k[b][h][pix] = kv;
            g_v[b][h][pix] = vv;
        }
    }
}

// ---------------------------------------------------------------------------
// Attention kernel: head_dim = 1 softmax over 4096 keys, flash-style.
// grid = (QCHUNKS, 8), 256 threads. k pre-scaled by log2(e) -> exp2 inner loop.
// ---------------------------------------------------------------------------
__global__ void attn_kernel()
{
    __shared__ float2 kv[LL];
    __shared__ float red[16];

    const int bh = blockIdx.y;
    const int b  = bh >> 2;
    const int h  = bh & 3;
    const int tid = threadIdx.x;
    const float LOG2E = 1.4426950408889634f;

    float lmax = -3.4e38f, lmin = 3.4e38f;
    for (int j = tid; j < LL; j += 256) {
        float ks = g_k[b][h][j] * LOG2E;
        float vv = g_v[b][h][j];
        kv[j] = make_float2(ks, vv);
        lmax = fmaxf(lmax, ks);
        lmin = fminf(lmin, ks);
    }
    #pragma unroll
    for (int o = 16; o > 0; o >>= 1) {
        lmax = fmaxf(lmax, __shfl_xor_sync(0xffffffffu, lmax, o));
        lmin = fminf(lmin, __shfl_xor_sync(0xffffffffu, lmin, o));
    }
    if ((tid & 31) == 0) { red[tid >> 5] = lmax; red[8 + (tid >> 5)] = lmin; }
    __syncthreads();
    float ksmax = red[0], ksmin = red[8];
    #pragma unroll
    for (int i = 1; i < 8; i++) {
        ksmax = fmaxf(ksmax, red[i]);
        ksmin = fminf(ksmin, red[8 + i]);
    }

    const int qi = blockIdx.x * QPB + tid;
    if (tid < QPB && qi < LL) {
        const float qv = g_q[b][h][qi];
        const float m2 = (qv >= 0.0f) ? qv * ksmax : qv * ksmin;  // exact row max (log2 domain)
        float num = 0.0f, den = 0.0f;
        #pragma unroll 8
        for (int j = 0; j < LL; j++) {
            float2 e2 = kv[j];
            float t = fmaf(qv, e2.x, -m2);
            float e;
            asm("ex2.approx.f32 %0, %1;" : "=f"(e) : "f"(t));
            den += e;
            num = fmaf(e, e2.y, num);
        }
        g_attn[b][h][qi] = num / den;
    }
}

// ---------------------------------------------------------------------------
// Epilogue: out_proj + 3x3 spatial conv on x + 1x1 output conv + dry/wet mix.
// grid = 32 blocks x 256 threads, 1 token each.
// ---------------------------------------------------------------------------
__global__ void epilogue_kernel(
    const float* __restrict__ x,
    const float* __restrict__ opw, const float* __restrict__ opb,
    const float* __restrict__ scw, const float* __restrict__ scb,
    const float* __restrict__ ocw, const float* __restrict__ ocb,
    float* __restrict__ out)
{
    const int t = blockIdx.x * 256 + threadIdx.x;   // 0..8191
    const int b   = t >> 12;
    const int pix = t & (LL - 1);
    const int py  = pix >> 6;
    const int px  = pix & 63;

    // wet2 = out_proj(attention)
    float o4[NHEADS];
    #pragma unroll
    for (int h = 0; h < NHEADS; h++) o4[h] = g_attn[b][h][pix];
    float wet2[CH];
    #pragma unroll
    for (int c = 0; c < CH; c++) {
        float a = __ldg(&opb[c]);
        #pragma unroll
        for (int h = 0; h < NHEADS; h++) a = fmaf(__ldg(&opw[c*CH + h]), o4[h], a);
        wet2[c] = a;
    }

    // spatial = conv3x3(x; sc_w) at this pixel (zero pad)
    float xin[CH][9];
    #pragma unroll
    for (int ci = 0; ci < CH; ci++)
        #pragma unroll
        for (int dy = 0; dy < 3; dy++)
            #pragma unroll
            for (int dx = 0; dx < 3; dx++) {
                int yy = py + dy - 1, xx = px + dx - 1;
                float v = 0.0f;
                if (yy >= 0 && yy < HH && xx >= 0 && xx < WW)
                    v = __ldg(&x[((b*CH + ci)*HH + yy)*WW + xx]);
                xin[ci][dy*3+dx] = v;
            }
    float sp[2*CH];
    #pragma unroll
    for (int j = 0; j < 2*CH; j++) {
        float a = __ldg(&scb[j]);
        #pragma unroll
        for (int ci = 0; ci < CH; ci++)
            #pragma unroll
            for (int kk = 0; kk < 9; kk++)
                a = fmaf(__ldg(&scw[(j*CH + ci)*9 + kk]), xin[ci][kk], a);
        sp[j] = a;
    }

    // processed = oc([spatial; wet2]); out = 0.7*x + 0.3*processed
    #pragma unroll
    for (int c = 0; c < CH; c++) {
        float a = __ldg(&ocb[c]);
        #pragma unroll
        for (int j = 0; j < 2*CH; j++) a = fmaf(__ldg(&ocw[c*12 + j]), sp[j], a);
        #pragma unroll
        for (int j = 0; j < CH; j++) a = fmaf(__ldg(&ocw[c*12 + 8 + j]), wet2[j], a);
        float xc = __ldg(&x[((b*CH + c)*HH + py)*WW + px]);
        out[((b*CH + c)*HH + py)*WW + px] = 0.7f * xc + 0.3f * a;
    }
}

// ---------------------------------------------------------------------------
extern "C" void kernel_launch(void* const* d_in, const int* in_sizes, int n_in,
                              void* d_out, int out_size)
{
    (void)in_sizes; (void)n_in; (void)out_size;
    const float* x      = (const float*)d_in[0];
    const float* refl_w = (const float*)d_in[1];
    const float* refl_d = (const float*)d_in[2];
    const float* sc_w   = (const float*)d_in[3];
    const float* sc_b   = (const float*)d_in[4];
    const float* fb_w   = (const float*)d_in[5];
    const float* fb_b   = (const float*)d_in[6];
    const float* d1_w   = (const float*)d_in[7];
    const float* d1_b   = (const float*)d_in[8];
    const float* d2_w   = (const float*)d_in[9];
    const float* d2_b   = (const float*)d_in[10];
    const float* ipw    = (const float*)d_in[11];
    const float* ipb    = (const float*)d_in[12];
    const float* opw    = (const float*)d_in[13];
    const float* opb    = (const float*)d_in[14];
    const float* oc_w   = (const float*)d_in[15];
    const float* oc_b   = (const float*)d_in[16];
    float* out = (float*)d_out;

    // Delay-kernel table (host, double precision, matches reference _gauss7)
    KTab kt;
    for (int r = 0; r < 4; r++)
        for (int c = 0; c < 7; c++) kt.k[r][c] = 0.0f;
    kt.k[0][3] = 1.0f;
    const int sizes[3] = {3, 5, 7};
    for (int ri = 0; ri < 3; ri++) {
        int ks = sizes[ri];
        double g[7], s = 0.0;
        for (int i = 0; i < ks; i++) {
            double xi = -2.0 + 4.0 * (double)i / (double)(ks - 1);
            g[i] = exp(-xi * xi);
            s += g[i];
        }
        int off = (7 - ks) / 2;
        for (int i = 0; i < ks; i++) kt.k[ri + 1][off + i] = (float)(g[i] / s);
    }

    for (int i = 0; i < 8; i++) {
        float pw8 = (float)pow(0.8, (double)i);
        reverb_iter_kernel<<<RB_BLOCKS, 256>>>(x, refl_w, refl_d, fb_w, fb_b,
                                               d1_w, d1_b, d2_w, d2_b,
                                               ipw, ipb, kt, i, pw8);
    }
    attn_kernel<<<dim3(QCHUNKS, 8), 256>>>();
    epilogue_kernel<<<(BATCH*LL + 255)/256, 256>>>(x, opw, opb, sc_w, sc_b, oc_w, oc_b, out);
}

// round 2
// speedup vs baseline: 1.4403x; 1.4403x over previous
#include <cuda_runtime.h>
#include <math.h>

#define BATCH 2
#define CH 4
#define HH 64
#define WW 64
#define LL (HH*WW)     // 4096
#define NHEADS 4
#define NB 128
#define NT 256

struct Params {
    float kern[4][7];  // delay kernel table
    float pw[8];       // 0.8^i
};

// ---------------- scratch (device globals; no allocation allowed) ----------
__device__ float g_fb[2][BATCH][CH][HH][WW];
__device__ float g_q[BATCH][NHEADS][LL];
__device__ float g_k[BATCH][NHEADS][LL];   // pre-scaled by log2(e)
__device__ float g_v[BATCH][NHEADS][LL];
__device__ float g_attn[BATCH][NHEADS][LL];
__device__ volatile unsigned g_gen;
__device__ unsigned g_count;

__device__ __forceinline__ float sigm(float x) {
    return __fdividef(1.0f, 1.0f + __expf(-x));
}

// grid-wide barrier (all NB blocks resident: single wave guaranteed)
__device__ __forceinline__ void gbar() {
    __syncthreads();
    if (threadIdx.x == 0) {
        unsigned gen = g_gen;
        __threadfence();                       // release my writes
        unsigned a = atomicAdd(&g_count, 1u);
        if (a == NB - 1u) {
            g_count = 0u;
            __threadfence();
            g_gen = gen + 1u;
        } else {
            while (g_gen == gen) __nanosleep(32);
        }
    }
    __syncthreads();
}

// ---------------------------------------------------------------------------
__global__ void __launch_bounds__(NT, 1) fused_kernel(
    const float* __restrict__ x,
    const float* __restrict__ refl_w,
    const float* __restrict__ refl_d,
    const float* __restrict__ sc_w, const float* __restrict__ sc_b,
    const float* __restrict__ fb_w, const float* __restrict__ fb_b,
    const float* __restrict__ d1_w, const float* __restrict__ d1_b,
    const float* __restrict__ d2_w, const float* __restrict__ d2_b,
    const float* __restrict__ ipw, const float* __restrict__ ipb,
    const float* __restrict__ opw, const float* __restrict__ opb,
    const float* __restrict__ ocw, const float* __restrict__ ocb,
    float* __restrict__ out, Params par)
{
    __shared__ float  s_blur[CH][3][WW + 2];  // blurred rows y-1..y+1, col-padded
    __shared__ float  s_refl[CH][WW];
    __shared__ float  s_wet[CH][WW];          // persistent wet for this row
    __shared__ float  s_w[CH * CH * 9];
    __shared__ float2 s_kv[LL];               // attention k(*log2e), v
    __shared__ float  s_red[16];

    const int tid   = threadIdx.x;
    const int blk   = blockIdx.x;
    const int batch = blk >> 6;
    const int y     = blk & 63;
    const int c4    = tid >> 6;   // channel 0..3
    const int col   = tid & 63;

    if (tid < CH * CH * 9) s_w[tid] = fb_w[tid];
    // zero the column padding of s_blur
    if (tid < 24) {
        int c = tid / 6, rem = tid % 6;
        s_blur[c][rem >> 1][(rem & 1) * (WW + 1)] = 0.0f;
    }
    s_wet[c4][col] = 0.0f;
    __syncthreads();

    const float LOG2E = 1.4426950408889634f;

    // =========================== reverb: 8 iterations ======================
    #pragma unroll 1
    for (int iter = 0; iter < 8; iter++) {
        const int src = (iter + 1) & 1;
        const int dst = iter & 1;

        int kidx = (int)floorf(__ldg(&refl_d[iter]) * 0.5f);
        kidx = min(max(kidx, 0), 3);
        const float* kr = par.kern[kidx];

        // --- load fb rows y-4..y+4 for (c4,col), vertical 7-tap blur ---
        float f[9];
        #pragma unroll
        for (int r = 0; r < 9; r++) {
            int yy = y - 4 + r;
            float v = 0.0f;
            if (yy >= 0 && yy < HH) {
                if (iter == 0)
                    v = __ldg(&x[((batch * CH + c4) * HH + yy) * WW + col]) * 0.1f;
                else
                    v = __ldcg(&g_fb[src][batch][c4][yy][col]);
            }
            f[r] = v;
        }
        const float fcen = f[4];   // fb at (y,col) — needed for fb update

        #pragma unroll
        for (int s = 0; s < 3; s++) {
            float acc = 0.0f;
            #pragma unroll
            for (int t7 = 0; t7 < 7; t7++)
                acc = fmaf(kr[t7], f[s + t7], acc);
            s_blur[c4][s][col + 1] = acc;
        }
        __syncthreads();

        // --- 3x3 conv (4->4): this thread computes output channel c4 ---
        float r_out = __ldg(&fb_b[c4]);
        #pragma unroll
        for (int ci = 0; ci < CH; ci++)
            #pragma unroll
            for (int dy = 0; dy < 3; dy++)
                #pragma unroll
                for (int dx = 0; dx < 3; dx++)
                    r_out = fmaf(s_w[(c4 * CH + ci) * 9 + dy * 3 + dx],
                                 s_blur[ci][dy][col + dx], r_out);
        s_refl[c4][col] = r_out;
        __syncthreads();

        // --- damp MLP per pixel (threads 0..63), overwrite s_refl with refl*damp
        if (tid < 64) {
            float rf[CH];
            #pragma unroll
            for (int c = 0; c < CH; c++) rf[c] = s_refl[c][tid];
            float s1[2];
            #pragma unroll
            for (int j = 0; j < 2; j++) {
                float h1 = __ldg(&d1_b[j]);
                #pragma unroll
                for (int c = 0; c < CH; c++)
                    h1 = fmaf(__ldg(&d1_w[j * CH + c]), rf[c], h1);
                s1[j] = h1 * sigm(h1);
            }
            #pragma unroll
            for (int c = 0; c < CH; c++) {
                float h2 = __ldg(&d2_b[c]);
                #pragma unroll
                for (int j = 0; j < 2; j++)
                    h2 = fmaf(__ldg(&d2_w[c * 2 + j]), s1[j], h2);
                s_refl[c][tid] = rf[c] * sigm(h2);
            }
        }
        __syncthreads();

        // --- accumulate wet (smem) and write fb ping-pong (global) ---
        const float wgt = sigm(__ldg(&refl_w[iter])) * par.pw[iter];
        const float rd  = s_refl[c4][col];
        s_wet[c4][col] += rd * wgt;
        g_fb[dst][batch][c4][y][col] = fmaf(rd, 0.04f, fcen);   // FEEDBACK*0.1

        // --- last iteration: QKV projection from wet (head_dim = 1) ---
        if (iter == 7) {
            __syncthreads();
            const int h   = c4;          // head = thread's channel group
            const int pix = y * WW + col;
            float wv[CH];
            #pragma unroll
            for (int c = 0; c < CH; c++) wv[c] = s_wet[c][col];
            float qv = __ldg(&ipb[h]);
            float kv = __ldg(&ipb[4 + h]);
            float vv = __ldg(&ipb[8 + h]);
            #pragma unroll
            for (int c = 0; c < CH; c++) {
                qv = fmaf(__ldg(&ipw[h * CH + c]),       wv[c], qv);
                kv = fmaf(__ldg(&ipw[(4 + h) * CH + c]), wv[c], kv);
                vv = fmaf(__ldg(&ipw[(8 + h) * CH + c]), wv[c], vv);
            }
            __stcg(&g_q[batch][h][pix], qv);
            __stcg(&g_k[batch][h][pix], kv * LOG2E);
            __stcg(&g_v[batch][h][pix], vv);
        }
        gbar();
    }

    // =========================== attention ================================
    {
        const int bh    = blk >> 4;     // 0..7
        const int chunk = blk & 15;     // 0..15
        const int b     = bh >> 2;
        const int h     = bh & 3;

        float lmax = -3.4e38f, lmin = 3.4e38f;
        for (int j = tid; j < LL; j += NT) {
            float ks = __ldcg(&g_k[b][h][j]);   // already * log2(e)
            float vv = __ldcg(&g_v[b][h][j]);
            s_kv[j] = make_float2(ks, vv);
            lmax = fmaxf(lmax, ks);
            lmin = fminf(lmin, ks);
        }
        #pragma unroll
        for (int o = 16; o > 0; o >>= 1) {
            lmax = fmaxf(lmax, __shfl_xor_sync(0xffffffffu, lmax, o));
            lmin = fminf(lmin, __shfl_xor_sync(0xffffffffu, lmin, o));
        }
        if ((tid & 31) == 0) { s_red[tid >> 5] = lmax; s_red[8 + (tid >> 5)] = lmin; }
        __syncthreads();
        float ksmax = s_red[0], ksmin = s_red[8];
        #pragma unroll
        for (int i = 1; i < 8; i++) {
            ksmax = fmaxf(ksmax, s_red[i]);
            ksmin = fminf(ksmin, s_red[8 + i]);
        }

        const int qi = chunk * NT + tid;           // 16*256 = 4096 exactly
        const float qv = __ldcg(&g_q[b][h][qi]);
        const float m2 = (qv >= 0.0f) ? qv * ksmax : qv * ksmin;  // exact row max
        float num = 0.0f, den = 0.0f;
        #pragma unroll 8
        for (int j = 0; j < LL; j++) {
            float2 e2 = s_kv[j];
            float t = fmaf(qv, e2.x, -m2);
            float e;
            asm("ex2.approx.f32 %0, %1;" : "=f"(e) : "f"(t));
            den += e;
            num = fmaf(e, e2.y, num);
        }
        __stcg(&g_attn[b][h][qi], num / den);
    }
    gbar();

    // =========================== epilogue (blocks 0..31) ===================
    if (blk < 32) {
        const int t   = blk * NT + tid;      // 0..8191
        const int b   = t >> 12;
        const int pix = t & (LL - 1);
        const int py  = pix >> 6;
        const int px  = pix & 63;

        // wet2 = out_proj(attention output)
        float o4[NHEADS];
        #pragma unroll
        for (int h = 0; h < NHEADS; h++) o4[h] = __ldcg(&g_attn[b][h][pix]);
        float wet2[CH];
        #pragma unroll
        for (int c = 0; c < CH; c++) {
            float a = __ldg(&opb[c]);
            #pragma unroll
            for (int h = 0; h < NHEADS; h++)
                a = fmaf(__ldg(&opw[c * CH + h]), o4[h], a);
            wet2[c] = a;
        }

        // spatial = conv3x3(x; sc_w) at this pixel (zero pad)
        float xin[CH][9];
        #pragma unroll
        for (int ci = 0; ci < CH; ci++)
            #pragma unroll
            for (int dy = 0; dy < 3; dy++)
                #pragma unroll
                for (int dx = 0; dx < 3; dx++) {
                    int yy = py + dy - 1, xx = px + dx - 1;
                    float v = 0.0f;
                    if (yy >= 0 && yy < HH && xx >= 0 && xx < WW)
                        v = __ldg(&x[((b * CH + ci) * HH + yy) * WW + xx]);
                    xin[ci][dy * 3 + dx] = v;
                }
        float sp[2 * CH];
        #pragma unroll
        for (int j = 0; j < 2 * CH; j++) {
            float a = __ldg(&sc_b[j]);
            #pragma unroll
            for (int ci = 0; ci < CH; ci++)
                #pragma unroll
                for (int kk = 0; kk < 9; kk++)
                    a = fmaf(__ldg(&sc_w[(j * CH + ci) * 9 + kk]), xin[ci][kk], a);
            sp[j] = a;
        }

        #pragma unroll
        for (int c = 0; c < CH; c++) {
            float a = __ldg(&ocb[c]);
            #pragma unroll
            for (int j = 0; j < 2 * CH; j++)
                a = fmaf(__ldg(&ocw[c * 12 + j]), sp[j], a);
            #pragma unroll
            for (int j = 0; j < CH; j++)
                a = fmaf(__ldg(&ocw[c * 12 + 8 + j]), wet2[j], a);
            float xc = __ldg(&x[((b * CH + c) * HH + py) * WW + px]);
            out[((b * CH + c) * HH + py) * WW + px] = 0.7f * xc + 0.3f * a;
        }
    }
}

// ---------------------------------------------------------------------------
extern "C" void kernel_launch(void* const* d_in, const int* in_sizes, int n_in,
                              void* d_out, int out_size)
{
    (void)in_sizes; (void)n_in; (void)out_size;
    const float* x      = (const float*)d_in[0];
    const float* refl_w = (const float*)d_in[1];
    const float* refl_d = (const float*)d_in[2];
    const float* sc_w   = (const float*)d_in[3];
    const float* sc_b   = (const float*)d_in[4];
    const float* fb_w   = (const float*)d_in[5];
    const float* fb_b   = (const float*)d_in[6];
    const float* d1_w   = (const float*)d_in[7];
    const float* d1_b   = (const float*)d_in[8];
    const float* d2_w   = (const float*)d_in[9];
    const float* d2_b   = (const float*)d_in[10];
    const float* ipw    = (const float*)d_in[11];
    const float* ipb    = (const float*)d_in[12];
    const float* opw    = (const float*)d_in[13];
    const float* opb    = (const float*)d_in[14];
    const float* oc_w   = (const float*)d_in[15];
    const float* oc_b   = (const float*)d_in[16];
    float* out = (float*)d_out;

    Params par;
    for (int r = 0; r < 4; r++)
        for (int c = 0; c < 7; c++) par.kern[r][c] = 0.0f;
    par.kern[0][3] = 1.0f;
    const int sizes[3] = {3, 5, 7};
    for (int ri = 0; ri < 3; ri++) {
        int ks = sizes[ri];
        double g[7], s = 0.0;
        for (int i = 0; i < ks; i++) {
            double xi = -2.0 + 4.0 * (double)i / (double)(ks - 1);
            g[i] = exp(-xi * xi);
            s += g[i];
        }
        int off = (7 - ks) / 2;
        for (int i = 0; i < ks; i++) par.kern[ri + 1][off + i] = (float)(g[i] / s);
    }
    for (int i = 0; i < 8; i++) par.pw[i] = (float)pow(0.8, (double)i);

    fused_kernel<<<NB, NT>>>(x, refl_w, refl_d, sc_w, sc_b, fb_w, fb_b,
                             d1_w, d1_b, d2_w, d2_b, ipw, ipb, opw, opb,
                             oc_w, oc_b, out, par);
}

// round 3
// speedup vs baseline: 2.8701x; 1.9927x over previous
#include <cuda_runtime.h>
#include <math.h>

#define BATCH 2
#define CH 4
#define HH 64
#define WW 64
#define LL (HH*WW)     // 4096
#define NHEADS 4
#define NB 128
#define NT 256
#define NNODE 32

struct Params {
    float kern[4][7];  // delay kernel table
    float pw[8];       // 0.8^i
};

// ---------------- scratch (device globals; no allocation allowed) ----------
__device__ float g_fb[2][BATCH][CH][HH][WW];
__device__ float g_q[BATCH][NHEADS][LL];
__device__ float g_k[BATCH][NHEADS][LL];   // pre-scaled by log2(e)
__device__ float g_v[BATCH][NHEADS][LL];
__device__ float g_attn[BATCH][NHEADS][LL];
__device__ volatile unsigned g_gen;
__device__ unsigned g_count;

__device__ __forceinline__ float sigm(float x) {
    return __fdividef(1.0f, 1.0f + __expf(-x));
}

// grid-wide barrier (all NB blocks resident: single wave guaranteed)
__device__ __forceinline__ void gbar() {
    __syncthreads();
    if (threadIdx.x == 0) {
        unsigned gen = g_gen;
        __threadfence();                       // release my writes
        unsigned a = atomicAdd(&g_count, 1u);
        if (a == NB - 1u) {
            g_count = 0u;
            __threadfence();
            g_gen = gen + 1u;
        } else {
            while (g_gen == gen) __nanosleep(32);
        }
    }
    __syncthreads();
}

// ---------------------------------------------------------------------------
__global__ void __launch_bounds__(NT, 1) fused_kernel(
    const float* __restrict__ x,
    const float* __restrict__ refl_w,
    const float* __restrict__ refl_d,
    const float* __restrict__ sc_w, const float* __restrict__ sc_b,
    const float* __restrict__ fb_w, const float* __restrict__ fb_b,
    const float* __restrict__ d1_w, const float* __restrict__ d1_b,
    const float* __restrict__ d2_w, const float* __restrict__ d2_b,
    const float* __restrict__ ipw, const float* __restrict__ ipb,
    const float* __restrict__ opw, const float* __restrict__ opb,
    const float* __restrict__ ocw, const float* __restrict__ ocb,
    float* __restrict__ out, Params par)
{
    __shared__ float  s_blur[CH][3][WW + 2];
    __shared__ float  s_refl[CH][WW];
    __shared__ float  s_wet[CH][WW];
    __shared__ float  s_w[CH * CH * 9];
    __shared__ float2 s_kv[LL];
    __shared__ float  s_q[NT];
    __shared__ float  s_nx[NNODE];
    __shared__ float  s_nR[NNODE];
    __shared__ float  s_red[32];
    __shared__ float  s_wgt[8];     // sigmoid(refl_w[i]) * 0.8^i
    __shared__ int    s_kidx[8];

    const int tid   = threadIdx.x;
    const int blk   = blockIdx.x;
    const int batch = blk >> 6;
    const int y     = blk & 63;
    const int c4    = tid >> 6;
    const int col   = tid & 63;

    if (tid < CH * CH * 9) s_w[tid] = fb_w[tid];
    if (tid < 24) {
        int c = tid / 6, rem = tid % 6;
        s_blur[c][rem >> 1][(rem & 1) * (WW + 1)] = 0.0f;
    }
    if (tid >= 32 && tid < 40) {
        int i = tid - 32;
        s_wgt[i] = sigm(__ldg(&refl_w[i])) * par.pw[i];
        int kidx = (int)floorf(__ldg(&refl_d[i]) * 0.5f);
        s_kidx[i] = min(max(kidx, 0), 3);
    }
    s_wet[c4][col] = 0.0f;

    // preload tiny weights into registers (avoid L2 reloads after L1 flushes)
    const float r_fbb = __ldg(&fb_b[c4]);
    float r_d1w[8], r_d2w[8], r_d1b[2], r_d2b[4];
    #pragma unroll
    for (int i = 0; i < 8; i++) { r_d1w[i] = __ldg(&d1_w[i]); r_d2w[i] = __ldg(&d2_w[i]); }
    r_d1b[0] = __ldg(&d1_b[0]); r_d1b[1] = __ldg(&d1_b[1]);
    #pragma unroll
    for (int i = 0; i < 4; i++) r_d2b[i] = __ldg(&d2_b[i]);
    __syncthreads();

    const float LOG2E = 1.4426950408889634f;

    // =========================== reverb: 8 iterations ======================
    #pragma unroll 1
    for (int iter = 0; iter < 8; iter++) {
        const int src = (iter + 1) & 1;
        const int dst = iter & 1;
        const float* kr = par.kern[s_kidx[iter]];

        float f[9];
        #pragma unroll
        for (int r = 0; r < 9; r++) {
            int yy = y - 4 + r;
            float v = 0.0f;
            if (yy >= 0 && yy < HH) {
                if (iter == 0)
                    v = __ldg(&x[((batch * CH + c4) * HH + yy) * WW + col]) * 0.1f;
                else
                    v = __ldcg(&g_fb[src][batch][c4][yy][col]);
            }
            f[r] = v;
        }
        const float fcen = f[4];

        #pragma unroll
        for (int s = 0; s < 3; s++) {
            float acc = 0.0f;
            #pragma unroll
            for (int t7 = 0; t7 < 7; t7++)
                acc = fmaf(kr[t7], f[s + t7], acc);
            s_blur[c4][s][col + 1] = acc;
        }
        __syncthreads();

        float r_out = r_fbb;
        #pragma unroll
        for (int ci = 0; ci < CH; ci++)
            #pragma unroll
            for (int dy = 0; dy < 3; dy++)
                #pragma unroll
                for (int dx = 0; dx < 3; dx++)
                    r_out = fmaf(s_w[(c4 * CH + ci) * 9 + dy * 3 + dx],
                                 s_blur[ci][dy][col + dx], r_out);
        s_refl[c4][col] = r_out;
        __syncthreads();

        if (tid < 64) {
            float rf[CH];
            #pragma unroll
            for (int c = 0; c < CH; c++) rf[c] = s_refl[c][tid];
            float s1[2];
            #pragma unroll
            for (int j = 0; j < 2; j++) {
                float h1 = r_d1b[j];
                #pragma unroll
                for (int c = 0; c < CH; c++)
                    h1 = fmaf(r_d1w[j * CH + c], rf[c], h1);
                s1[j] = h1 * sigm(h1);
            }
            #pragma unroll
            for (int c = 0; c < CH; c++) {
                float h2 = r_d2b[c];
                #pragma unroll
                for (int j = 0; j < 2; j++)
                    h2 = fmaf(r_d2w[c * 2 + j], s1[j], h2);
                s_refl[c][tid] = rf[c] * sigm(h2);
            }
        }
        __syncthreads();

        const float rd = s_refl[c4][col];
        s_wet[c4][col] += rd * s_wgt[iter];
        g_fb[dst][batch][c4][y][col] = fmaf(rd, 0.04f, fcen);

        if (iter == 7) {
            __syncthreads();
            const int h   = c4;
            const int pix = y * WW + col;
            float wv[CH];
            #pragma unroll
            for (int c = 0; c < CH; c++) wv[c] = s_wet[c][col];
            float qv = __ldg(&ipb[h]);
            float kv = __ldg(&ipb[4 + h]);
            float vv = __ldg(&ipb[8 + h]);
            #pragma unroll
            for (int c = 0; c < CH; c++) {
                qv = fmaf(__ldg(&ipw[h * CH + c]),       wv[c], qv);
                kv = fmaf(__ldg(&ipw[(4 + h) * CH + c]), wv[c], kv);
                vv = fmaf(__ldg(&ipw[(8 + h) * CH + c]), wv[c], vv);
            }
            __stcg(&g_q[batch][h][pix], qv);
            __stcg(&g_k[batch][h][pix], kv * LOG2E);
            __stcg(&g_v[batch][h][pix], vv);
        }
        gbar();
    }

    // =========================== attention ================================
    {
        const int bh    = blk >> 4;
        const int chunk = blk & 15;
        const int b     = bh >> 2;
        const int h     = bh & 3;

        float kmx = -3.4e38f, kmn = 3.4e38f, qmx = -3.4e38f, qmn = 3.4e38f;
        #pragma unroll 4
        for (int i = 0; i < 16; i++) {
            int j = i * NT + tid;
            float ks = __ldcg(&g_k[b][h][j]);
            float vv = __ldcg(&g_v[b][h][j]);
            s_kv[j] = make_float2(ks, vv);
            kmx = fmaxf(kmx, ks); kmn = fminf(kmn, ks);
            float qv = __ldcg(&g_q[b][h][j]);
            qmx = fmaxf(qmx, qv); qmn = fminf(qmn, qv);
            if (i == chunk) s_q[tid] = qv;
        }
        #pragma unroll
        for (int o = 16; o > 0; o >>= 1) {
            kmx = fmaxf(kmx, __shfl_xor_sync(0xffffffffu, kmx, o));
            kmn = fminf(kmn, __shfl_xor_sync(0xffffffffu, kmn, o));
            qmx = fmaxf(qmx, __shfl_xor_sync(0xffffffffu, qmx, o));
            qmn = fminf(qmn, __shfl_xor_sync(0xffffffffu, qmn, o));
        }
        const int wrp = tid >> 5;
        if ((tid & 31) == 0) {
            s_red[wrp] = kmx; s_red[8 + wrp] = kmn;
            s_red[16 + wrp] = qmx; s_red[24 + wrp] = qmn;
        }
        __syncthreads();
        float ksmax = s_red[0], ksmin = s_red[8], qmax_ = s_red[16], qmin_ = s_red[24];
        #pragma unroll
        for (int i = 1; i < 8; i++) {
            ksmax = fmaxf(ksmax, s_red[i]);
            ksmin = fminf(ksmin, s_red[8 + i]);
            qmax_ = fmaxf(qmax_, s_red[16 + i]);
            qmin_ = fminf(qmin_, s_red[24 + i]);
        }

        const float dq = qmax_ - qmin_;
        const float dk = ksmax - ksmin;           // log2 units
        const bool use_interp = (dq * dk <= 16.0f);

        if (use_interp) {
            // Chebyshev-Lobatto nodes on padded [qmin, qmax]
            const float pad = 1e-4f * (fabsf(qmin_) + fabsf(qmax_)) + 1e-12f;
            const float a0 = qmin_ - pad, b0 = qmax_ + pad;
            const float cen = 0.5f * (a0 + b0), rad = 0.5f * (b0 - a0);
            if (tid < NNODE)
                s_nx[tid] = cen + rad * cosf((float)tid * (3.14159265358979323f / (NNODE - 1)));
            __syncthreads();

            // exact evaluation of R(q_t) at 32 nodes (8 threads per node)
            const int t   = tid >> 3;
            const int sub = tid & 7;
            const float qt = s_nx[t];
            const float m2 = (qt >= 0.0f) ? qt * ksmax : qt * ksmin;
            float num = 0.0f, den = 0.0f;
            #pragma unroll 8
            for (int i = 0; i < LL / 8; i++) {
                float2 e2 = s_kv[i * 8 + sub];
                float tt = fmaf(qt, e2.x, -m2);
                float e;
                asm("ex2.approx.f32 %0, %1;" : "=f"(e) : "f"(tt));
                den += e;
                num = fmaf(e, e2.y, num);
            }
            #pragma unroll
            for (int o = 4; o > 0; o >>= 1) {
                num += __shfl_xor_sync(0xffffffffu, num, o);
                den += __shfl_xor_sync(0xffffffffu, den, o);
            }
            if (sub == 0) s_nR[t] = num / den;
            __syncthreads();

            // barycentric interpolation for this block's 256 queries
            const float q = s_q[tid];
            float bn = 0.0f, bd = 0.0f;
            #pragma unroll
            for (int t2 = 0; t2 < NNODE; t2++) {
                float d = q - s_nx[t2];
                if (d == 0.0f) d = 1e-30f;
                float w = ((t2 == 0) || (t2 == NNODE - 1)) ? 0.5f : 1.0f;
                w = (t2 & 1) ? -w : w;
                float r = __fdividef(w, d);
                bn = fmaf(r, s_nR[t2], bn);
                bd += r;
            }
            __stcg(&g_attn[b][h][chunk * NT + tid], bn / bd);
        } else {
            // exact fallback (spread too large for safe interpolation)
            const float qv = s_q[tid];
            const float m2 = (qv >= 0.0f) ? qv * ksmax : qv * ksmin;
            float num = 0.0f, den = 0.0f;
            #pragma unroll 8
            for (int j = 0; j < LL; j++) {
                float2 e2 = s_kv[j];
                float tt = fmaf(qv, e2.x, -m2);
                float e;
                asm("ex2.approx.f32 %0, %1;" : "=f"(e) : "f"(tt));
                den += e;
                num = fmaf(e, e2.y, num);
            }
            __stcg(&g_attn[b][h][chunk * NT + tid], num / den);
        }
    }
    gbar();

    // =========================== epilogue (blocks 0..31) ===================
    if (blk < 32) {
        const int t   = blk * NT + tid;
        const int b   = t >> 12;
        const int pix = t & (LL - 1);
        const int py  = pix >> 6;
        const int px  = pix & 63;

        float o4[NHEADS];
        #pragma unroll
        for (int h = 0; h < NHEADS; h++) o4[h] = __ldcg(&g_attn[b][h][pix]);
        float wet2[CH];
        #pragma unroll
        for (int c = 0; c < CH; c++) {
            float a = __ldg(&opb[c]);
            #pragma unroll
            for (int h = 0; h < NHEADS; h++)
                a = fmaf(__ldg(&opw[c * CH + h]), o4[h], a);
            wet2[c] = a;
        }

        float xin[CH][9];
        #pragma unroll
        for (int ci = 0; ci < CH; ci++)
            #pragma unroll
            for (int dy = 0; dy < 3; dy++)
                #pragma unroll
                for (int dx = 0; dx < 3; dx++) {
                    int yy = py + dy - 1, xx = px + dx - 1;
                    float v = 0.0f;
                    if (yy >= 0 && yy < HH && xx >= 0 && xx < WW)
                        v = __ldg(&x[((b * CH + ci) * HH + yy) * WW + xx]);
                    xin[ci][dy * 3 + dx] = v;
                }
        float sp[2 * CH];
        #pragma unroll
        for (int j = 0; j < 2 * CH; j++) {
            float a = __ldg(&sc_b[j]);
            #pragma unroll
            for (int ci = 0; ci < CH; ci++)
                #pragma unroll
                for (int kk = 0; kk < 9; kk++)
                    a = fmaf(__ldg(&sc_w[(j * CH + ci) * 9 + kk]), xin[ci][kk], a);
            sp[j] = a;
        }

        #pragma unroll
        for (int c = 0; c < CH; c++) {
            float a = __ldg(&ocb[c]);
            #pragma unroll
            for (int j = 0; j < 2 * CH; j++)
                a = fmaf(__ldg(&ocw[c * 12 + j]), sp[j], a);
            #pragma unroll
            for (int j = 0; j < CH; j++)
                a = fmaf(__ldg(&ocw[c * 12 + 8 + j]), wet2[j], a);
            float xc = __ldg(&x[((b * CH + c) * HH + py) * WW + px]);
            out[((b * CH + c) * HH + py) * WW + px] = 0.7f * xc + 0.3f * a;
        }
    }
}

// ---------------------------------------------------------------------------
extern "C" void kernel_launch(void* const* d_in, const int* in_sizes, int n_in,
                              void* d_out, int out_size)
{
    (void)in_sizes; (void)n_in; (void)out_size;
    const float* x      = (const float*)d_in[0];
    const float* refl_w = (const float*)d_in[1];
    const float* refl_d = (const float*)d_in[2];
    const float* sc_w   = (const float*)d_in[3];
    const float* sc_b   = (const float*)d_in[4];
    const float* fb_w   = (const float*)d_in[5];
    const float* fb_b   = (const float*)d_in[6];
    const float* d1_w   = (const float*)d_in[7];
    const float* d1_b   = (const float*)d_in[8];
    const float* d2_w   = (const float*)d_in[9];
    const float* d2_b   = (const float*)d_in[10];
    const float* ipw    = (const float*)d_in[11];
    const float* ipb    = (const float*)d_in[12];
    const float* opw    = (const float*)d_in[13];
    const float* opb    = (const float*)d_in[14];
    const float* oc_w   = (const float*)d_in[15];
    const float* oc_b   = (const float*)d_in[16];
    float* out = (float*)d_out;

    Params par;
    for (int r = 0; r < 4; r++)
        for (int c = 0; c < 7; c++) par.kern[r][c] = 0.0f;
    par.kern[0][3] = 1.0f;
    const int sizes[3] = {3, 5, 7};
    for (int ri = 0; ri < 3; ri++) {
        int ks = sizes[ri];
        double g[7], s = 0.0;
        for (int i = 0; i < ks; i++) {
            double xi = -2.0 + 4.0 * (double)i / (double)(ks - 1);
            g[i] = exp(-xi * xi);
            s += g[i];
        }
        int off = (7 - ks) / 2;
        for (int i = 0; i < ks; i++) par.kern[ri + 1][off + i] = (float)(g[i] / s);
    }
    for (int i = 0; i < 8; i++) par.pw[i] = (float)pow(0.8, (double)i);

    fused_kernel<<<NB, NT>>>(x, refl_w, refl_d, sc_w, sc_b, fb_w, fb_b,
                             d1_w, d1_b, d2_w, d2_b, ipw, ipb, opw, opb,
                             oc_w, oc_b, out, par);
}

// round 4
// speedup vs baseline: 3.7339x; 1.3010x over previous
#include <cuda_runtime.h>
#include <math.h>

#define BATCH 2
#define CH 4
#define HH 64
#define WW 64
#define LL (HH*WW)     // 4096
#define NHEADS 4
#define NB 128
#define NT 256
#define NNODE 32

struct Params {
    float kern[4][7];  // delay kernel table
    float pw[8];       // 0.8^i
};

// ---------------- scratch (device globals; no allocation allowed) ----------
__device__ float g_fb[2][BATCH][CH][HH][WW];
__device__ float g_q[BATCH][NHEADS][LL];
__device__ float g_k[BATCH][NHEADS][LL];   // pre-scaled by log2(e)
__device__ float g_v[BATCH][NHEADS][LL];
__device__ float g_attn[BATCH][NHEADS][LL];
__device__ float g_nodes[BATCH*NHEADS][NNODE];
__device__ unsigned g_rowflag[NB];          // reverb wavefront flags (reset each launch)
__device__ unsigned g_qkvcnt[BATCH];
__device__ unsigned g_nodecnt[BATCH*NHEADS];
__device__ volatile unsigned g_gen;
__device__ unsigned g_count;

__device__ __forceinline__ float sigm(float x) {
    return __fdividef(1.0f, 1.0f + __expf(-x));
}

// full grid barrier (all NB blocks resident: single wave guaranteed)
__device__ __forceinline__ void gbar() {
    __syncthreads();
    if (threadIdx.x == 0) {
        unsigned gen = g_gen;
        __threadfence();
        unsigned a = atomicAdd(&g_count, 1u);
        if (a == NB - 1u) {
            g_count = 0u;
            __threadfence();
            g_gen = gen + 1u;
        } else {
            while (g_gen == gen) __nanosleep(32);
        }
    }
    __syncthreads();
}

// ---------------------------------------------------------------------------
__global__ void __launch_bounds__(NT, 1) fused_kernel(
    const float* __restrict__ x,
    const float* __restrict__ refl_w,
    const float* __restrict__ refl_d,
    const float* __restrict__ sc_w, const float* __restrict__ sc_b,
    const float* __restrict__ fb_w, const float* __restrict__ fb_b,
    const float* __restrict__ d1_w, const float* __restrict__ d1_b,
    const float* __restrict__ d2_w, const float* __restrict__ d2_b,
    const float* __restrict__ ipw, const float* __restrict__ ipb,
    const float* __restrict__ opw, const float* __restrict__ opb,
    const float* __restrict__ ocw, const float* __restrict__ ocb,
    float* __restrict__ out, Params par)
{
    __shared__ float  s_blur[CH][3][WW + 2];
    __shared__ float  s_w[CH * CH * 9];
    __shared__ float2 s_kv[LL];
    __shared__ float  s_q[NT];
    __shared__ float  s_nx[NNODE];
    __shared__ float  s_nR[NNODE];
    __shared__ float  s_red[32];
    __shared__ float  s_wgt[8];
    __shared__ int    s_kidx[8];

    const int tid   = threadIdx.x;
    const int blk   = blockIdx.x;
    const int batch = blk >> 6;
    const int y     = blk & 63;
    // pixel-major mapping: 4 channels of a pixel in 4 adjacent lanes
    const int c   = tid & 3;
    const int col = tid >> 2;
    const int lane = tid & 31;

    if (tid < CH * CH * 9) s_w[tid] = fb_w[tid];
    if (tid < 24) {               // zero column padding of s_blur
        int cc = tid / 6, rem = tid % 6;
        s_blur[cc][rem >> 1][(rem & 1) * (WW + 1)] = 0.0f;
    }
    if (tid >= 32 && tid < 40) {
        int i = tid - 32;
        s_wgt[i] = sigm(__ldg(&refl_w[i])) * par.pw[i];
        int kidx = (int)floorf(__ldg(&refl_d[i]) * 0.5f);
        s_kidx[i] = min(max(kidx, 0), 3);
    }

    // per-lane weight preloads (lane's channel = c)
    const float r_fbb  = __ldg(&fb_b[c]);
    float r_d1w[8], r_d1b2[2];
    #pragma unroll
    for (int i = 0; i < 8; i++) r_d1w[i] = __ldg(&d1_w[i]);
    r_d1b2[0] = __ldg(&d1_b[0]); r_d1b2[1] = __ldg(&d1_b[1]);
    const float r_d2b  = __ldg(&d2_b[c]);
    const float r_d2w0 = __ldg(&d2_w[c * 2 + 0]);
    const float r_d2w1 = __ldg(&d2_w[c * 2 + 1]);
    __syncthreads();

    const float LOG2E = 1.4426950408889634f;

    float wet = 0.0f;
    float fb_self = 0.0f;

    // =========================== reverb: 8 iterations ======================
    #pragma unroll 1
    for (int iter = 0; iter < 8; iter++) {
        const int src = (iter + 1) & 1;
        const int dst = iter & 1;
        const float* kr = par.kern[s_kidx[iter]];

        float f[9];
        if (iter == 0) {
            #pragma unroll
            for (int r = 0; r < 9; r++) {
                int yy = y - 4 + r;
                f[r] = (yy >= 0 && yy < HH)
                     ? __ldg(&x[((batch * CH + c) * HH + yy) * WW + col]) * 0.1f : 0.0f;
            }
        } else {
            #pragma unroll
            for (int r = 0; r < 9; r++) {
                if (r == 4) { f[4] = fb_self; continue; }
                int yy = y - 4 + r;
                f[r] = (yy >= 0 && yy < HH)
                     ? __ldcg(&g_fb[src][batch][c][yy][col]) : 0.0f;
            }
        }
        const float fcen = f[4];

        #pragma unroll
        for (int s = 0; s < 3; s++) {
            float acc = 0.0f;
            #pragma unroll
            for (int t7 = 0; t7 < 7; t7++)
                acc = fmaf(kr[t7], f[s + t7], acc);
            int gy = y - 1 + s;
            s_blur[c][s][col + 1] = ((unsigned)gy < (unsigned)HH) ? acc : 0.0f;
        }
        __syncthreads();

        // 3x3 conv: lane computes its out-channel c for pixel col
        float r_out = r_fbb;
        #pragma unroll
        for (int ci = 0; ci < CH; ci++)
            #pragma unroll
            for (int dy = 0; dy < 3; dy++)
                #pragma unroll
                for (int dx = 0; dx < 3; dx++)
                    r_out = fmaf(s_w[(c * CH + ci) * 9 + dy * 3 + dx],
                                 s_blur[ci][dy][col + dx], r_out);

        // gather the 4 channels of this pixel via shfl (lanes grouped by 4)
        const int lb = lane & ~3;
        float rf[4];
        #pragma unroll
        for (int k = 0; k < 4; k++)
            rf[k] = __shfl_sync(0xffffffffu, r_out, lb + k);

        // damp MLP (computed redundantly per lane; own channel output)
        float s1[2];
        #pragma unroll
        for (int j = 0; j < 2; j++) {
            float h1 = r_d1b2[j];
            #pragma unroll
            for (int cc = 0; cc < CH; cc++)
                h1 = fmaf(r_d1w[j * CH + cc], rf[cc], h1);
            s1[j] = h1 * sigm(h1);
        }
        float h2 = fmaf(r_d2w0, s1[0], fmaf(r_d2w1, s1[1], r_d2b));
        const float rd = r_out * sigm(h2);

        wet = fmaf(rd, s_wgt[iter], wet);
        fb_self = fmaf(rd, 0.04f, fcen);

        if (iter < 7) {
            __stcg(&g_fb[dst][batch][c][y][col], fb_self);
            // ---- neighbor wavefront sync ----
            __syncthreads();                 // all stores issued block-wide
            if (tid == 0) {
                __threadfence();             // publish fb row
                atomicExch(&g_rowflag[blk], (unsigned)(iter + 1));
            }
            if (tid < 8) {
                int off = (tid < 4) ? (tid - 4) : (tid - 3);   // -4..-1, 1..4
                int ny = y + off;
                if (ny >= 0 && ny < HH) {
                    volatile unsigned* fl = (volatile unsigned*)&g_rowflag[blk + off];
                    while (*fl < (unsigned)(iter + 1)) __nanosleep(20);
                }
            }
            __syncthreads();
        } else {
            // ---- QKV projection (head = lane channel) ----
            float wf[4];
            #pragma unroll
            for (int k = 0; k < 4; k++)
                wf[k] = __shfl_sync(0xffffffffu, wet, lb + k);
            const int pix = y * WW + col;
            float qv = __ldg(&ipb[c]);
            float kv = __ldg(&ipb[4 + c]);
            float vv = __ldg(&ipb[8 + c]);
            #pragma unroll
            for (int cc = 0; cc < CH; cc++) {
                qv = fmaf(__ldg(&ipw[c * CH + cc]),       wf[cc], qv);
                kv = fmaf(__ldg(&ipw[(4 + c) * CH + cc]), wf[cc], kv);
                vv = fmaf(__ldg(&ipw[(8 + c) * CH + cc]), wf[cc], vv);
            }
            __stcg(&g_q[batch][c][pix], qv);
            __stcg(&g_k[batch][c][pix], kv * LOG2E);
            __stcg(&g_v[batch][c][pix], vv);
            __syncthreads();
            if (tid == 0) {
                __threadfence();
                atomicAdd(&g_qkvcnt[batch], 1u);
            }
        }
    }

    // ===================== attention: phase B (node eval) ==================
    const int bh    = blk >> 4;      // 0..7
    const int chunk = blk & 15;      // 0..15
    const int b     = bh >> 2;
    const int h     = bh & 3;

    if (tid == 0) {
        volatile unsigned* p = (volatile unsigned*)&g_qkvcnt[b];
        while (*p < 64u) __nanosleep(20);
    }
    __syncthreads();

    float kmx = -3.4e38f, kmn = 3.4e38f, qmx = -3.4e38f, qmn = 3.4e38f;
    #pragma unroll 4
    for (int i = 0; i < 16; i++) {
        int j = i * NT + tid;
        float ks = __ldcg(&g_k[b][h][j]);
        float vv = __ldcg(&g_v[b][h][j]);
        s_kv[j] = make_float2(ks, vv);
        kmx = fmaxf(kmx, ks); kmn = fminf(kmn, ks);
        float qv = __ldcg(&g_q[b][h][j]);
        qmx = fmaxf(qmx, qv); qmn = fminf(qmn, qv);
        if (i == chunk) s_q[tid] = qv;
    }
    #pragma unroll
    for (int o = 16; o > 0; o >>= 1) {
        kmx = fmaxf(kmx, __shfl_xor_sync(0xffffffffu, kmx, o));
        kmn = fminf(kmn, __shfl_xor_sync(0xffffffffu, kmn, o));
        qmx = fmaxf(qmx, __shfl_xor_sync(0xffffffffu, qmx, o));
        qmn = fminf(qmn, __shfl_xor_sync(0xffffffffu, qmn, o));
    }
    const int wrp = tid >> 5;
    if (lane == 0) {
        s_red[wrp] = kmx; s_red[8 + wrp] = kmn;
        s_red[16 + wrp] = qmx; s_red[24 + wrp] = qmn;
    }
    __syncthreads();
    float ksmax = s_red[0], ksmin = s_red[8], qmax_ = s_red[16], qmin_ = s_red[24];
    #pragma unroll
    for (int i = 1; i < 8; i++) {
        ksmax = fmaxf(ksmax, s_red[i]);
        ksmin = fminf(ksmin, s_red[8 + i]);
        qmax_ = fmaxf(qmax_, s_red[16 + i]);
        qmin_ = fminf(qmin_, s_red[24 + i]);
    }

    const float dq = qmax_ - qmin_;
    const float dk = ksmax - ksmin;
    const bool use_interp = (dq * dk <= 16.0f);

    // Chebyshev-Lobatto nodes on padded [qmin, qmax] (identical on all blocks)
    const float pad = 1e-4f * (fabsf(qmin_) + fabsf(qmax_)) + 1e-12f;
    const float a0 = qmin_ - pad, b0 = qmax_ + pad;
    const float cen = 0.5f * (a0 + b0), rad = 0.5f * (b0 - a0);
    if (tid < NNODE)
        s_nx[tid] = cen + rad * cosf((float)tid * (3.14159265358979323f / (NNODE - 1)));
    __syncthreads();

    if (use_interp) {
        // this block evaluates 2 nodes: 2*chunk + (tid>>7), 128 threads each
        const int node    = 2 * chunk + (tid >> 7);
        const int lane128 = tid & 127;
        const float qt = s_nx[node];
        const float m2 = (qt >= 0.0f) ? qt * ksmax : qt * ksmin;
        float num = 0.0f, den = 0.0f;
        #pragma unroll 8
        for (int i = 0; i < LL / 128; i++) {
            float2 e2 = s_kv[i * 128 + lane128];
            float tt = fmaf(qt, e2.x, -m2);
            float e;
            asm("ex2.approx.f32 %0, %1;" : "=f"(e) : "f"(tt));
            den += e;
            num = fmaf(e, e2.y, num);
        }
        #pragma unroll
        for (int o = 16; o > 0; o >>= 1) {
            num += __shfl_xor_sync(0xffffffffu, num, o);
            den += __shfl_xor_sync(0xffffffffu, den, o);
        }
        if (lane == 0) { s_red[wrp] = num; s_red[8 + wrp] = den; }
        __syncthreads();
        if (tid == 0 || tid == 128) {
            int base = (tid >> 7) * 4;
            float N = 0.0f, D = 0.0f;
            #pragma unroll
            for (int w2 = 0; w2 < 4; w2++) { N += s_red[base + w2]; D += s_red[8 + base + w2]; }
            __stcg(&g_nodes[bh][node], N / D);
        }
    }
    __syncthreads();
    if (tid == 0) {
        __threadfence();
        atomicAdd(&g_nodecnt[bh], 1u);
    }

    // ===================== attention: phase C (interpolate) ================
    if (tid == 0) {
        volatile unsigned* p = (volatile unsigned*)&g_nodecnt[bh];
        while (*p < 16u) __nanosleep(20);
    }
    __syncthreads();

    if (use_interp) {
        if (tid < NNODE) s_nR[tid] = __ldcg(&g_nodes[bh][tid]);
        __syncthreads();
        const float q = s_q[tid];
        float bn = 0.0f, bd = 0.0f;
        #pragma unroll
        for (int t2 = 0; t2 < NNODE; t2++) {
            float d = q - s_nx[t2];
            if (d == 0.0f) d = 1e-30f;
            float w = ((t2 == 0) || (t2 == NNODE - 1)) ? 0.5f : 1.0f;
            w = (t2 & 1) ? -w : w;
            float r = __fdividef(w, d);
            bn = fmaf(r, s_nR[t2], bn);
            bd += r;
        }
        __stcg(&g_attn[b][h][chunk * NT + tid], bn / bd);
    } else {
        // exact fallback
        const float qv = s_q[tid];
        const float m2 = (qv >= 0.0f) ? qv * ksmax : qv * ksmin;
        float num = 0.0f, den = 0.0f;
        #pragma unroll 8
        for (int j = 0; j < LL; j++) {
            float2 e2 = s_kv[j];
            float tt = fmaf(qv, e2.x, -m2);
            float e;
            asm("ex2.approx.f32 %0, %1;" : "=f"(e) : "f"(tt));
            den += e;
            num = fmaf(e, e2.y, num);
        }
        __stcg(&g_attn[b][h][chunk * NT + tid], num / den);
    }

    gbar();   // everything published; also fences attn stores

    // reset cross-block state for the next graph replay (no readers after gbar)
    if (tid == 0) {
        atomicExch(&g_rowflag[blk], 0u);
        if (blk < BATCH) atomicExch(&g_qkvcnt[blk], 0u);
        if (blk < BATCH * NHEADS) atomicExch(&g_nodecnt[blk], 0u);
    }

    // =========================== epilogue: 64 pixels per block =============
    if (tid < 64) {
        const int t   = blk * 64 + tid;       // 0..8191
        const int eb  = t >> 12;
        const int pix = t & (LL - 1);
        const int py  = pix >> 6;
        const int px  = pix & 63;

        float o4[NHEADS];
        #pragma unroll
        for (int hh2 = 0; hh2 < NHEADS; hh2++) o4[hh2] = __ldcg(&g_attn[eb][hh2][pix]);
        float wet2[CH];
        #pragma unroll
        for (int cc = 0; cc < CH; cc++) {
            float a = __ldg(&opb[cc]);
            #pragma unroll
            for (int hh2 = 0; hh2 < NHEADS; hh2++)
                a = fmaf(__ldg(&opw[cc * CH + hh2]), o4[hh2], a);
            wet2[cc] = a;
        }

        float xin[CH][9];
        #pragma unroll
        for (int ci = 0; ci < CH; ci++)
            #pragma unroll
            for (int dy = 0; dy < 3; dy++)
                #pragma unroll
                for (int dx = 0; dx < 3; dx++) {
                    int yy = py + dy - 1, xx = px + dx - 1;
                    float v = 0.0f;
                    if (yy >= 0 && yy < HH && xx >= 0 && xx < WW)
                        v = __ldg(&x[((eb * CH + ci) * HH + yy) * WW + xx]);
                    xin[ci][dy * 3 + dx] = v;
                }
        float sp[2 * CH];
        #pragma unroll
        for (int j = 0; j < 2 * CH; j++) {
            float a = __ldg(&sc_b[j]);
            #pragma unroll
            for (int ci = 0; ci < CH; ci++)
                #pragma unroll
                for (int kk = 0; kk < 9; kk++)
                    a = fmaf(__ldg(&sc_w[(j * CH + ci) * 9 + kk]), xin[ci][kk], a);
            sp[j] = a;
        }

        #pragma unroll
        for (int cc = 0; cc < CH; cc++) {
            float a = __ldg(&ocb[cc]);
            #pragma unroll
            for (int j = 0; j < 2 * CH; j++)
                a = fmaf(__ldg(&ocw[cc * 12 + j]), sp[j], a);
            #pragma unroll
            for (int j = 0; j < CH; j++)
                a = fmaf(__ldg(&ocw[cc * 12 + 8 + j]), wet2[j], a);
            float xc = __ldg(&x[((eb * CH + cc) * HH + py) * WW + px]);
            out[((eb * CH + cc) * HH + py) * WW + px] = 0.7f * xc + 0.3f * a;
        }
    }
}

// ---------------------------------------------------------------------------
extern "C" void kernel_launch(void* const* d_in, const int* in_sizes, int n_in,
                              void* d_out, int out_size)
{
    (void)in_sizes; (void)n_in; (void)out_size;
    const float* x      = (const float*)d_in[0];
    const float* refl_w = (const float*)d_in[1];
    const float* refl_d = (const float*)d_in[2];
    const float* sc_w   = (const float*)d_in[3];
    const float* sc_b   = (const float*)d_in[4];
    const float* fb_w   = (const float*)d_in[5];
    const float* fb_b   = (const float*)d_in[6];
    const float* d1_w   = (const float*)d_in[7];
    const float* d1_b   = (const float*)d_in[8];
    const float* d2_w   = (const float*)d_in[9];
    const float* d2_b   = (const float*)d_in[10];
    const float* ipw    = (const float*)d_in[11];
    const float* ipb    = (const float*)d_in[12];
    const float* opw    = (const float*)d_in[13];
    const float* opb    = (const float*)d_in[14];
    const float* oc_w   = (const float*)d_in[15];
    const float* oc_b   = (const float*)d_in[16];
    float* out = (float*)d_out;

    Params par;
    for (int r = 0; r < 4; r++)
        for (int c = 0; c < 7; c++) par.kern[r][c] = 0.0f;
    par.kern[0][3] = 1.0f;
    const int sizes[3] = {3, 5, 7};
    for (int ri = 0; ri < 3; ri++) {
        int ks = sizes[ri];
        double g[7], s = 0.0;
        for (int i = 0; i < ks; i++) {
            double xi = -2.0 + 4.0 * (double)i / (double)(ks - 1);
            g[i] = exp(-xi * xi);
            s += g[i];
        }
        int off = (7 - ks) / 2;
        for (int i = 0; i < ks; i++) par.kern[ri + 1][off + i] = (float)(g[i] / s);
    }
    for (int i = 0; i < 8; i++) par.pw[i] = (float)pow(0.8, (double)i);

    fused_kernel<<<NB, NT>>>(x, refl_w, refl_d, sc_w, sc_b, fb_w, fb_b,
                             d1_w, d1_b, d2_w, d2_b, ipw, ipb, opw, opb,
                             oc_w, oc_b, out, par);
}